// round 15
// baseline (speedup 1.0000x reference)
#include <cuda_runtime.h>
#include <cuda_fp16.h>
#include <cstdint>
#include <cstddef>

// ---------------- problem constants ----------------
#define BATCH   256
#define NTOK    50
#define NP      7
#define HID     256
#define HEADS   8
#define DH      32
#define MLPD    1024
#define OUTD    1000
#define PS      32
#define IMG     224
#define INPUTD  3072
#define ROWS    (BATCH*NTOK)      // 12800
#define PROWS   (BATCH*NP*NP)     // 12544
#define EMAX    512

// ---------------- device scratch ----------------
__device__ float g_x[ROWS*HID];
__device__ float g_y[ROWS*HID];
__device__ float g_h[ROWS*HID];
__device__ float g_mlp[ROWS*MLPD];
__device__ float g_part[4*PROWS*HID];   // split-K partials (patch embed)
__device__ float g_als[ROWS*HEADS];
__device__ float g_ald[ROWS*HEADS];
__device__ float g_logits[BATCH*OUTD];
__device__ int   g_csr_ptr[NTOK+1];
__device__ int   g_csr_src[1024];

// ---------------- helpers ----------------
__device__ __forceinline__ float warpSum(float v){
    #pragma unroll
    for (int o=16;o;o>>=1) v += __shfl_xor_sync(0xffffffffu, v, o);
    return v;
}
__device__ __forceinline__ float warpMax(float v){
    #pragma unroll
    for (int o=16;o;o>>=1) v = fmaxf(v, __shfl_xor_sync(0xffffffffu, v, o));
    return v;
}
__device__ __forceinline__ float blockSum(float v, float* sm){
    int lane = threadIdx.x & 31, w = threadIdx.x >> 5;
    v = warpSum(v);
    if (lane == 0) sm[w] = v;
    __syncthreads();
    if (threadIdx.x == 0){
        float s = 0.f;
        for (int i = 0; i < 8; i++) s += sm[i];
        sm[8] = s;
    }
    __syncthreads();
    return sm[8];
}
__device__ __forceinline__ float blockMax(float v, float* sm){
    int lane = threadIdx.x & 31, w = threadIdx.x >> 5;
    v = warpMax(v);
    if (lane == 0) sm[w] = v;
    __syncthreads();
    if (threadIdx.x == 0){
        float s = sm[0];
        for (int i = 1; i < 8; i++) s = fmaxf(s, sm[i]);
        sm[8] = s;
    }
    __syncthreads();
    return sm[8];
}
__device__ __forceinline__ float gelu_exact(float v){
    return 0.5f * v * (1.0f + erff(v * 0.7071067811865475f));
}
__device__ __forceinline__ void hilo_pack(float x, float y, unsigned& uh, unsigned& ul){
    __half hx = __float2half_rn(x);
    __half hy = __float2half_rn(y);
    __half lx = __float2half_rn(x - __half2float(hx));
    __half ly = __float2half_rn(y - __half2float(hy));
    __half2 th = __halves2half2(hx, hy);
    __half2 tl = __halves2half2(lx, ly);
    uh = *reinterpret_cast<unsigned*>(&th);
    ul = *reinterpret_cast<unsigned*>(&tl);
}
__device__ __forceinline__ unsigned h_pack(float x, float y){
    __half2 t = __halves2half2(__float2half_rn(x), __float2half_rn(y));
    return *reinterpret_cast<unsigned*>(&t);
}
__device__ __forceinline__ void mma_f16(float* d, const unsigned* a, const unsigned* b){
    asm volatile(
        "mma.sync.aligned.m16n8k16.row.col.f32.f16.f16.f32 "
        "{%0,%1,%2,%3}, {%4,%5,%6,%7}, {%8,%9}, {%0,%1,%2,%3};\n"
        : "+f"(d[0]), "+f"(d[1]), "+f"(d[2]), "+f"(d[3])
        : "r"(a[0]), "r"(a[1]), "r"(a[2]), "r"(a[3]), "r"(b[0]), "r"(b[1]));
}

// =============================================================
// 2xFP16 tensor GEMM: D = (Ah+Al) @ Bh. 128x128x32 tile, double-buffered,
// 2 CTAs/SM. SK = split-K factor (blockIdx.z = split index).
// SK > 1: raw partial writes to C[z*M + row][*].
// MODE 0: C = A@B ; MODE 2: gelu(A@B+bias) ; MODE 3: C += A@B+bias
// MODE 4: patch-embed (image gather) ; MODE 5: C = A@B + fused att logits
// =============================================================
template<int MODE, int SK>
__global__ __launch_bounds__(256, 2)
void tgemm(const float* __restrict__ A, int lda,
           const float* __restrict__ B, int ldb,
           float* __restrict__ C, int ldc,
           int M, int N, int K,
           const float* __restrict__ bias,
           const float* __restrict__ att_src, const float* __restrict__ att_dst,
           float* __restrict__ als, float* __restrict__ ald)
{
    extern __shared__ unsigned dsm[];   // per stage 6144 u32: sAh/sAl/sBh

    const int tx   = threadIdx.x;
    const int wid  = tx >> 5;
    const int lane = tx & 31;
    const int warp_m = wid >> 2;
    const int warp_n = wid & 3;
    const int bm = blockIdx.y * 128;
    const int bn = blockIdx.x * 128;
    const int Ksub = K / SK;
    const int kb   = Ksub * blockIdx.z;

    const int a_m  = tx >> 3;
    const int a_kv = tx & 7;
    const int b_q  = tx & 31;

    float acc[4][4][4] = {};

    float4 ar[4];
    float4 br0[2], br1[2];

    auto load_stage = [&](int k0){
        #pragma unroll
        for (int it = 0; it < 4; it++){
            int m = a_m + 32*it;
            if (MODE == 4){
                int mg = bm + m;
                int gb = mg / (NP*NP);
                int p  = mg % (NP*NP);
                int gi = p / NP, gj = p % NP;
                int k  = k0 + a_kv*4;
                int c  = k >> 10;
                int rem = k & 1023;
                int hh = rem >> 5, ww = rem & 31;
                size_t off = ((size_t)(gb*3 + c) * IMG + (gi*PS + hh)) * IMG + gj*PS + ww;
                ar[it] = *(const float4*)(A + off);
            } else {
                ar[it] = *(const float4*)(A + (size_t)(bm + m) * lda + k0 + a_kv*4);
            }
        }
        #pragma unroll
        for (int it = 0; it < 2; it++){
            int krow = (wid << 1) + (it << 4);
            br0[it] = *(const float4*)(B + (size_t)(k0 + krow    ) * ldb + bn + b_q*4);
            br1[it] = *(const float4*)(B + (size_t)(k0 + krow + 1) * ldb + bn + b_q*4);
        }
    };

    auto store_stage = [&](int buf){
        unsigned* sAh = dsm + buf*6144;
        unsigned* sAl = sAh + 2048;
        unsigned* sBh = sAh + 4096;
        #pragma unroll
        for (int it = 0; it < 4; it++){
            int m   = a_m + 32*it;
            int ks  = a_kv >> 2;
            int c   = (a_kv & 3) << 2;
            int kp0 = c >> 1;
            int g   = (m >> 4)*2 + ks;
            int reg = ((m & 15) >> 3) + ((kp0 & 4) ? 2 : 0);
            int lane0 = (m & 7)*4 + (kp0 & 3);
            int base = g*128 + reg*32;
            unsigned uh, ul;
            hilo_pack(ar[it].x, ar[it].y, uh, ul);
            sAh[base + lane0]     = uh;  sAl[base + lane0]     = ul;
            hilo_pack(ar[it].z, ar[it].w, uh, ul);
            sAh[base + lane0 + 1] = uh;  sAl[base + lane0 + 1] = ul;
        }
        #pragma unroll
        for (int it = 0; it < 2; it++){
            int reg = (wid >> 2) & 1;
            int w3  = wid & 3;
            const float* r0 = (const float*)&br0[it];
            const float* r1 = (const float*)&br1[it];
            #pragma unroll
            for (int j = 0; j < 4; j++){
                int n  = b_q*4 + j;
                int g  = (n >> 3)*2 + it;
                int s  = (n >> 3) & 7;
                int ln = (((n & 7)*4 + w3) ^ s);
                sBh[g*64 + reg*32 + ln] = h_pack(r0[j], r1[j]);
            }
        }
    };

    auto compute = [&](int buf){
        unsigned* sAh = dsm + buf*6144;
        unsigned* sAl = sAh + 2048;
        unsigned* sBh = sAh + 4096;
        #pragma unroll
        for (int ks = 0; ks < 2; ks++){
            unsigned ah[4][4], al[4][4];
            unsigned bh[4][2];
            #pragma unroll
            for (int mt = 0; mt < 4; mt++){
                int g = (warp_m*4 + mt)*2 + ks;
                int base = g*128;
                #pragma unroll
                for (int r = 0; r < 4; r++){
                    ah[mt][r] = sAh[base + r*32 + lane];
                    al[mt][r] = sAl[base + r*32 + lane];
                }
            }
            #pragma unroll
            for (int nt = 0; nt < 4; nt++){
                int ntile = warp_n*4 + nt;
                int g  = ntile*2 + ks;
                int ln = lane ^ (ntile & 7);
                bh[nt][0] = sBh[g*64 + ln];   bh[nt][1] = sBh[g*64 + 32 + ln];
            }
            #pragma unroll
            for (int mt = 0; mt < 4; mt++)
                #pragma unroll
                for (int nt = 0; nt < 4; nt++){
                    mma_f16(acc[mt][nt], al[mt], bh[nt]);
                    mma_f16(acc[mt][nt], ah[mt], bh[nt]);
                }
        }
    };

    load_stage(kb);
    store_stage(0);
    __syncthreads();

    const int NS = Ksub / 32;
    for (int kt = 0; kt < NS; kt++){
        if (kt + 1 < NS) load_stage(kb + (kt + 1) * 32);
        compute(kt & 1);
        if (kt + 1 < NS){
            store_stage((kt + 1) & 1);
            __syncthreads();
        }
    }

    // hoisted attention vectors (MODE 5): depend only on nt and lane&3
    const int head = (MODE == 5) ? ((bn >> 5) + warp_n) : 0;
    float as0[4], as1[4], ad0[4], ad1[4];
    if (MODE == 5){
        #pragma unroll
        for (int nt = 0; nt < 4; nt++){
            int ch = nt*8 + ((lane & 3) << 1);
            as0[nt] = att_src[head*32 + ch];
            as1[nt] = att_src[head*32 + ch + 1];
            ad0[nt] = att_dst[head*32 + ch];
            ad1[nt] = att_dst[head*32 + ch + 1];
        }
    }

    // ---- epilogue ----
    #pragma unroll
    for (int mt = 0; mt < 4; mt++){
        int r0 = bm + warp_m*64 + mt*16 + (lane >> 2);
        #pragma unroll
        for (int half = 0; half < 2; half++){
            int row = r0 + half*8;
            if (SK > 1){
                float* cp = C + ((size_t)blockIdx.z * M + row) * ldc
                              + bn + warp_n*32 + ((lane & 3) << 1);
                #pragma unroll
                for (int nt = 0; nt < 4; nt++){
                    float2 o;
                    o.x = acc[mt][nt][half*2 + 0];
                    o.y = acc[mt][nt][half*2 + 1];
                    *(float2*)(cp + nt*8) = o;
                }
                continue;
            }
            if (MODE == 5){
                float ps = 0.f, pd = 0.f;
                #pragma unroll
                for (int nt = 0; nt < 4; nt++){
                    int c0 = bn + warp_n*32 + nt*8 + ((lane & 3) << 1);
                    float v0 = acc[mt][nt][half*2 + 0];
                    float v1 = acc[mt][nt][half*2 + 1];
                    float2 o; o.x = v0; o.y = v1;
                    *(float2*)(C + (size_t)row * ldc + c0) = o;
                    ps += v0*as0[nt] + v1*as1[nt];
                    pd += v0*ad0[nt] + v1*ad1[nt];
                }
                ps += __shfl_xor_sync(0xffffffffu, ps, 1);
                ps += __shfl_xor_sync(0xffffffffu, ps, 2);
                pd += __shfl_xor_sync(0xffffffffu, pd, 1);
                pd += __shfl_xor_sync(0xffffffffu, pd, 2);
                if ((lane & 3) == 0){
                    als[(size_t)row * HEADS + head] = ps;
                    ald[(size_t)row * HEADS + head] = pd;
                }
                continue;
            }
            int orow = row;
            int tpos = 0;
            if (MODE == 4){
                int b = row / (NP*NP);
                int p = row % (NP*NP);
                tpos = p + 1;
                orow = b * NTOK + tpos;
            }
            #pragma unroll
            for (int nt = 0; nt < 4; nt++){
                int c0 = bn + warp_n*32 + nt*8 + ((lane & 3) << 1);
                float v0 = acc[mt][nt][half*2 + 0];
                float v1 = acc[mt][nt][half*2 + 1];
                if (MODE >= 2){ v0 += bias[c0]; v1 += bias[c0+1]; }
                if (MODE == 2){ v0 = gelu_exact(v0); v1 = gelu_exact(v1); }
                if (MODE == 4){
                    float fac = expf(-(float)c0 * 0.03597789207803285f);
                    float ang = (float)tpos * fac;
                    float s, c;
                    sincosf(ang, &s, &c);
                    v0 += s; v1 += c;
                }
                float* cp = C + (size_t)orow * ldc + c0;
                if (MODE == 3){
                    float2 old = *(const float2*)cp;
                    v0 += old.x; v1 += old.y;
                }
                float2 o; o.x = v0; o.y = v1;
                *(float2*)cp = o;
            }
        }
    }
}

// ---- combine kernel for patch-embed split-K ----
__global__ __launch_bounds__(256)
void combine_embed(const float* __restrict__ part, const float* __restrict__ bias,
                   float* __restrict__ x){
    int i = blockIdx.x * 256 + threadIdx.x;     // over PROWS*HID/2
    int c0  = (i * 2) % HID;
    int row = (i * 2) / HID;
    float2 s = make_float2(0.f, 0.f);
    #pragma unroll
    for (int z = 0; z < 4; z++){
        float2 v = *(const float2*)(part + ((size_t)z * PROWS + row) * HID + c0);
        s.x += v.x; s.y += v.y;
    }
    int b = row / (NP*NP);
    int p = row % (NP*NP);
    int tpos = p + 1;
    float fac = expf(-(float)c0 * 0.03597789207803285f);
    float sv, cv;
    sincosf((float)tpos * fac, &sv, &cv);
    s.x += bias[c0]   + sv;
    s.y += bias[c0+1] + cv;
    *(float2*)(x + ((size_t)(b * NTOK + tpos)) * HID + c0) = s;
}

// ---------------- SIMT GEMM (small head GEMM: +bias) ----------------
__global__ __launch_bounds__(256)
void gemm64(const float* __restrict__ A, int lda,
            const float* __restrict__ B, int ldb,
            float* __restrict__ C, int ldc,
            int M, int N, int K,
            const float* __restrict__ bias)
{
    __shared__ float As[16][64];
    __shared__ float Bs[16][68];

    const int tx = threadIdx.x;
    const int bm = blockIdx.y * 64;
    const int bn = blockIdx.x * 64;

    const int am  = tx >> 2;
    const int ak  = (tx & 3) << 2;
    const int bk  = tx >> 4;
    const int bnn = (tx & 15) << 2;
    const int tm  = (tx >> 4) << 2;
    const int tn  = (tx & 15) << 2;

    const int arow = bm + am;

    float acc[4][4];
    #pragma unroll
    for (int i=0;i<4;i++)
        #pragma unroll
        for (int j=0;j<4;j++) acc[i][j] = 0.f;

    for (int k0 = 0; k0 < K; k0 += 16){
        float4 av = make_float4(0.f,0.f,0.f,0.f);
        if (arow < M)
            av = *(const float4*)(A + (size_t)arow * lda + k0 + ak);
        As[ak+0][am] = av.x; As[ak+1][am] = av.y;
        As[ak+2][am] = av.z; As[ak+3][am] = av.w;

        float4 bv = make_float4(0.f,0.f,0.f,0.f);
        if (bn + bnn < N)
            bv = *(const float4*)(B + (size_t)(k0 + bk) * ldb + bn + bnn);
        *(float4*)&Bs[bk][bnn] = bv;

        __syncthreads();
        #pragma unroll
        for (int kk = 0; kk < 16; kk++){
            float4 a = *(const float4*)&As[kk][tm];
            float4 b = *(const float4*)&Bs[kk][tn];
            acc[0][0] += a.x*b.x; acc[0][1] += a.x*b.y; acc[0][2] += a.x*b.z; acc[0][3] += a.x*b.w;
            acc[1][0] += a.y*b.x; acc[1][1] += a.y*b.y; acc[1][2] += a.y*b.z; acc[1][3] += a.y*b.w;
            acc[2][0] += a.z*b.x; acc[2][1] += a.z*b.y; acc[2][2] += a.z*b.z; acc[2][3] += a.z*b.w;
            acc[3][0] += a.w*b.x; acc[3][1] += a.w*b.y; acc[3][2] += a.w*b.z; acc[3][3] += a.w*b.w;
        }
        __syncthreads();
    }

    #pragma unroll
    for (int i=0;i<4;i++){
        int row = bm + tm + i;
        if (row >= M) continue;
        #pragma unroll
        for (int j=0;j<4;j++){
            int col = bn + tn + j;
            if (col >= N) continue;
            C[(size_t)row * ldc + col] = acc[i][j] + bias[col];
        }
    }
}

// ---------------- CLS token init ----------------
__global__ void cls_init_kernel(const float* __restrict__ cls, float* __restrict__ x){
    int b = blockIdx.x, c = threadIdx.x;
    x[(size_t)b * NTOK * HID + c] = cls[c] + ((c & 1) ? 1.0f : 0.0f);
}

// ---------------- CSR build ----------------
__global__ void build_csr_kernel(const int* __restrict__ edge_index, int E){
    __shared__ int s_src[EMAX], s_dst[EMAX], cnt[NTOK];
    int t = threadIdx.x;
    for (int e = t; e < E; e += 64){
        s_src[e] = edge_index[e];
        s_dst[e] = edge_index[E + e];
    }
    __syncthreads();
    if (t < NTOK){
        int c = 1;
        for (int e = 0; e < E; e++) if (s_dst[e] == t) c++;
        cnt[t] = c;
    }
    __syncthreads();
    if (t == 0){
        int s = 0;
        for (int n = 0; n < NTOK; n++){ g_csr_ptr[n] = s; s += cnt[n]; }
        g_csr_ptr[NTOK] = s;
    }
    __syncthreads();
    if (t < NTOK){
        int pos = g_csr_ptr[t];
        for (int e = 0; e < E; e++) if (s_dst[e] == t) g_csr_src[pos++] = s_src[e];
        g_csr_src[pos++] = t;
    }
}

// ---------------- LayerNorm (warp-per-row, float out) ----------------
__global__ __launch_bounds__(256)
void ln_kernel(const float* __restrict__ x, float* __restrict__ y,
               const float* __restrict__ g, const float* __restrict__ b){
    int row  = blockIdx.x * 8 + (threadIdx.x >> 5);
    int lane = threadIdx.x & 31;
    const float* xr = x + (size_t)row * HID;
    float4 v0 = *(const float4*)(xr + lane*4);
    float4 v1 = *(const float4*)(xr + 128 + lane*4);
    float s = v0.x+v0.y+v0.z+v0.w + v1.x+v1.y+v1.z+v1.w;
    float mu = warpSum(s) * (1.0f / HID);
    float d0x=v0.x-mu, d0y=v0.y-mu, d0z=v0.z-mu, d0w=v0.w-mu;
    float d1x=v1.x-mu, d1y=v1.y-mu, d1z=v1.z-mu, d1w=v1.w-mu;
    float q = d0x*d0x+d0y*d0y+d0z*d0z+d0w*d0w + d1x*d1x+d1y*d1y+d1z*d1z+d1w*d1w;
    float var = warpSum(q) * (1.0f / HID);
    float inv = rsqrtf(var + 1e-5f);
    float4 g0 = *(const float4*)(g + lane*4);
    float4 g1 = *(const float4*)(g + 128 + lane*4);
    float4 b0 = *(const float4*)(b + lane*4);
    float4 b1 = *(const float4*)(b + 128 + lane*4);
    float* yr = y + (size_t)row * HID;
    float4 o0, o1;
    o0.x = d0x*inv*g0.x + b0.x; o0.y = d0y*inv*g0.y + b0.y;
    o0.z = d0z*inv*g0.z + b0.z; o0.w = d0w*inv*g0.w + b0.w;
    o1.x = d1x*inv*g1.x + b1.x; o1.y = d1y*inv*g1.y + b1.y;
    o1.z = d1z*inv*g1.z + b1.z; o1.w = d1w*inv*g1.w + b1.w;
    *(float4*)(yr + lane*4) = o0;
    *(float4*)(yr + 128 + lane*4) = o1;
}

// ---- fused: edge softmax + GAT aggregation + bias + residual + LN2 ----
__global__ __launch_bounds__(256)
void gat_fused_kernel(const float* __restrict__ h,
                      const float* __restrict__ als, const float* __restrict__ ald,
                      const float* __restrict__ bias, float* __restrict__ x,
                      float* __restrict__ y,
                      const float* __restrict__ g2, const float* __restrict__ b2){
    __shared__ float alpha_s[HEADS][64];
    __shared__ float sm[9];
    int b = blockIdx.x / NTOK, n = blockIdx.x % NTOK;
    int c = threadIdx.x;
    int head = c >> 5, lane = c & 31;
    int base = g_csr_ptr[n], deg = g_csr_ptr[n+1] - base;

    {
        float aldv = ald[(size_t)(b * NTOK + n) * HEADS + head];
        float m = -1e30f;
        for (int p = lane; p < deg; p += 32){
            int src = g_csr_src[base + p];
            float e = als[(size_t)(b * NTOK + src) * HEADS + head] + aldv;
            e = (e > 0.f) ? e : 0.2f * e;
            alpha_s[head][p] = e;
            m = fmaxf(m, e);
        }
        m = warpMax(m);
        float s = 0.f;
        for (int p = lane; p < deg; p += 32){
            float ex = expf(alpha_s[head][p] - m);
            alpha_s[head][p] = ex;
            s += ex;
        }
        s = warpSum(s);
        float inv = 1.0f / (s + 1e-16f);
        for (int p = lane; p < deg; p += 32)
            alpha_s[head][p] *= inv;
    }
    __syncthreads();

    float acc = 0.f;
    for (int p = 0; p < deg; p++){
        int src = g_csr_src[base + p];
        acc += alpha_s[head][p] * h[(size_t)(b * NTOK + src) * HID + c];
    }
    size_t idx = (size_t)(b * NTOK + n) * HID + c;
    float v = x[idx] + acc + bias[c];
    x[idx] = v;

    float mu = blockSum(v, sm) * (1.0f / HID);
    float d = v - mu;
    float var = blockSum(d * d, sm) * (1.0f / HID);
    float inv = rsqrtf(var + 1e-5f);
    y[idx] = d * inv * g2[c] + b2[c];
}

// ---------------- final row softmax ----------------
__global__ __launch_bounds__(256)
void softmax_kernel(const float* __restrict__ logits, float* __restrict__ out){
    __shared__ float sm[9];
    int row = blockIdx.x, t = threadIdx.x;
    float v[4];
    float m = -1e30f;
    #pragma unroll
    for (int k = 0; k < 4; k++){
        int c = t + k * 256;
        v[k] = (c < OUTD) ? logits[(size_t)row * OUTD + c] : -1e30f;
        m = fmaxf(m, v[k]);
    }
    m = blockMax(m, sm);
    float s = 0.f;
    #pragma unroll
    for (int k = 0; k < 4; k++){
        v[k] = expf(v[k] - m);
        int c = t + k * 256;
        if (c < OUTD) s += v[k];
    }
    s = blockSum(s, sm);
    float inv = 1.0f / s;
    #pragma unroll
    for (int k = 0; k < 4; k++){
        int c = t + k * 256;
        if (c < OUTD) out[(size_t)row * OUTD + c] = v[k] * inv;
    }
}

#define TG_SMEM (48*1024)

// ---------------- host launch ----------------
extern "C" void kernel_launch(void* const* d_in, const int* in_sizes, int n_in,
                              void* d_out, int out_size)
{
    const float* images  = (const float*)d_in[0];
    const int*   eidx    = (const int*)  d_in[1];
    const float* Wmap    = (const float*)d_in[2];
    const float* bmap    = (const float*)d_in[3];
    const float* cls_tok = (const float*)d_in[4];
    const float* Wgat    = (const float*)d_in[5];
    const float* att_src = (const float*)d_in[6];
    const float* att_dst = (const float*)d_in[7];
    const float* bgat    = (const float*)d_in[8];
    const float* ln1_g   = (const float*)d_in[9];
    const float* ln1_b   = (const float*)d_in[10];
    const float* ln2_g   = (const float*)d_in[11];
    const float* ln2_b   = (const float*)d_in[12];
    const float* W1      = (const float*)d_in[13];
    const float* b1      = (const float*)d_in[14];
    const float* W2      = (const float*)d_in[15];
    const float* b2      = (const float*)d_in[16];
    const float* Wout    = (const float*)d_in[17];
    const float* bout    = (const float*)d_in[18];

    int E = in_sizes[1] / 2;

    float *x, *y, *h, *mlp, *part, *als, *ald, *logits;
    cudaGetSymbolAddress((void**)&x,      g_x);
    cudaGetSymbolAddress((void**)&y,      g_y);
    cudaGetSymbolAddress((void**)&h,      g_h);
    cudaGetSymbolAddress((void**)&mlp,    g_mlp);
    cudaGetSymbolAddress((void**)&part,   g_part);
    cudaGetSymbolAddress((void**)&als,    g_als);
    cudaGetSymbolAddress((void**)&ald,    g_ald);
    cudaGetSymbolAddress((void**)&logits, g_logits);

    cudaFuncSetAttribute((const void*)tgemm<5,1>, cudaFuncAttributeMaxDynamicSharedMemorySize, TG_SMEM);
    cudaFuncSetAttribute((const void*)tgemm<2,1>, cudaFuncAttributeMaxDynamicSharedMemorySize, TG_SMEM);
    cudaFuncSetAttribute((const void*)tgemm<3,1>, cudaFuncAttributeMaxDynamicSharedMemorySize, TG_SMEM);
    cudaFuncSetAttribute((const void*)tgemm<4,4>, cudaFuncAttributeMaxDynamicSharedMemorySize, TG_SMEM);

    // patch embed: split-K=4 into partials, then combine(+bias+posemb+remap)
    tgemm<4,4><<<dim3(HID/128, PROWS/128, 4), 256, TG_SMEM>>>(
        images, 0, Wmap, HID, part, HID, PROWS, HID, INPUTD, nullptr,
        nullptr, nullptr, nullptr, nullptr);
    combine_embed<<<PROWS*HID/512, 256>>>(part, bmap, x);
    cls_init_kernel<<<BATCH, HID>>>(cls_tok, x);
    build_csr_kernel<<<1, 64>>>(eidx, E);

    for (int l = 0; l < 4; l++){
        ln_kernel<<<ROWS/8, 256>>>(x, y, ln1_g + l*HID, ln1_b + l*HID);
        // Wgat GEMM with fused attention logit dots
        tgemm<5,1><<<dim3(HID/128, ROWS/128), 256, TG_SMEM>>>(
            y, HID, Wgat + (size_t)l*HID*HID, HID,
            h, HID, ROWS, HID, HID, nullptr,
            att_src + l*HID, att_dst + l*HID, als, ald);
        gat_fused_kernel<<<ROWS, 256>>>(h, als, ald, bgat + l*HID, x, y,
                                        ln2_g + l*HID, ln2_b + l*HID);

        tgemm<2,1><<<dim3(MLPD/128, ROWS/128), 256, TG_SMEM>>>(
            y, HID, W1 + (size_t)l*HID*MLPD, MLPD,
            mlp, MLPD, ROWS, MLPD, HID, b1 + l*MLPD,
            nullptr, nullptr, nullptr, nullptr);
        tgemm<3,1><<<dim3(HID/128, ROWS/128), 256, TG_SMEM>>>(
            mlp, MLPD, W2 + (size_t)l*MLPD*HID, HID,
            x, HID, ROWS, HID, MLPD, b2 + l*HID,
            nullptr, nullptr, nullptr, nullptr);
    }

    gemm64<<<dim3((OUTD+63)/64, BATCH/64), 256>>>(x, NTOK*HID, Wout, OUTD,
                                                  logits, OUTD, BATCH, OUTD, HID, bout);
    softmax_kernel<<<BATCH, 256>>>(logits, (float*)d_out);
    (void)n_in; (void)out_size;
}

// round 16
// speedup vs baseline: 1.0830x; 1.0830x over previous
#include <cuda_runtime.h>
#include <cuda_fp16.h>
#include <cstdint>
#include <cstddef>

// ---------------- problem constants ----------------
#define BATCH   256
#define NTOK    50
#define NP      7
#define HID     256
#define HEADS   8
#define DH      32
#define MLPD    1024
#define OUTD    1000
#define PS      32
#define IMG     224
#define INPUTD  3072
#define ROWS    (BATCH*NTOK)      // 12800
#define PROWS   (BATCH*NP*NP)     // 12544
#define EMAX    512

// smem layout strides (u32), padded to avoid bank alignment across groups
#define ASTRIDE 132               // 16 A-groups
#define BSTRIDE 66                // 32 B-groups
#define STAGEU  (16*ASTRIDE*2 + 32*BSTRIDE)   // 6336 u32 per stage
#define TG_SMEM (2*STAGEU*4)                  // 50688 B

// ---------------- device scratch ----------------
__device__ float g_x[ROWS*HID];
__device__ float g_y[ROWS*HID];
__device__ float g_h[ROWS*HID];
__device__ float g_mlp[ROWS*MLPD];
__device__ float g_part[4*PROWS*HID];   // split-K partials (patch embed)
__device__ float g_als[ROWS*HEADS];
__device__ float g_ald[ROWS*HEADS];
__device__ float g_logits[BATCH*OUTD];
__device__ int   g_csr_ptr[NTOK+1];
__device__ int   g_csr_src[1024];

// ---------------- helpers ----------------
__device__ __forceinline__ float warpSum(float v){
    #pragma unroll
    for (int o=16;o;o>>=1) v += __shfl_xor_sync(0xffffffffu, v, o);
    return v;
}
__device__ __forceinline__ float warpMax(float v){
    #pragma unroll
    for (int o=16;o;o>>=1) v = fmaxf(v, __shfl_xor_sync(0xffffffffu, v, o));
    return v;
}
__device__ __forceinline__ float blockSum(float v, float* sm){
    int lane = threadIdx.x & 31, w = threadIdx.x >> 5;
    v = warpSum(v);
    if (lane == 0) sm[w] = v;
    __syncthreads();
    if (threadIdx.x == 0){
        float s = 0.f;
        for (int i = 0; i < 8; i++) s += sm[i];
        sm[8] = s;
    }
    __syncthreads();
    return sm[8];
}
__device__ __forceinline__ float blockMax(float v, float* sm){
    int lane = threadIdx.x & 31, w = threadIdx.x >> 5;
    v = warpMax(v);
    if (lane == 0) sm[w] = v;
    __syncthreads();
    if (threadIdx.x == 0){
        float s = sm[0];
        for (int i = 1; i < 8; i++) s = fmaxf(s, sm[i]);
        sm[8] = s;
    }
    __syncthreads();
    return sm[8];
}
__device__ __forceinline__ float gelu_exact(float v){
    return 0.5f * v * (1.0f + erff(v * 0.7071067811865475f));
}
__device__ __forceinline__ void hilo_pack(float x, float y, unsigned& uh, unsigned& ul){
    __half hx = __float2half_rn(x);
    __half hy = __float2half_rn(y);
    __half lx = __float2half_rn(x - __half2float(hx));
    __half ly = __float2half_rn(y - __half2float(hy));
    __half2 th = __halves2half2(hx, hy);
    __half2 tl = __halves2half2(lx, ly);
    uh = *reinterpret_cast<unsigned*>(&th);
    ul = *reinterpret_cast<unsigned*>(&tl);
}
__device__ __forceinline__ unsigned h_pack(float x, float y){
    __half2 t = __halves2half2(__float2half_rn(x), __float2half_rn(y));
    return *reinterpret_cast<unsigned*>(&t);
}
__device__ __forceinline__ void mma_f16(float* d, const unsigned* a, const unsigned* b){
    asm volatile(
        "mma.sync.aligned.m16n8k16.row.col.f32.f16.f16.f32 "
        "{%0,%1,%2,%3}, {%4,%5,%6,%7}, {%8,%9}, {%0,%1,%2,%3};\n"
        : "+f"(d[0]), "+f"(d[1]), "+f"(d[2]), "+f"(d[3])
        : "r"(a[0]), "r"(a[1]), "r"(a[2]), "r"(a[3]), "r"(b[0]), "r"(b[1]));
}

// =============================================================
// 2xFP16 tensor GEMM: D = (Ah+Al) @ Bh. 128x128x32 tile, double-buffered,
// 2 CTAs/SM. Fragment-major smem: A [g][lane][4reg] (LDS.128 reads),
// B [g][lane][2reg] (LDS.64 reads).
// SK>1 (blockIdx.z): raw partials to C[z*M+row][*].
// MODE 0: C=A@B ; 2: gelu(A@B+bias) ; 3: C+=A@B+bias ; 4: patch-embed gather
// =============================================================
template<int MODE, int SK>
__global__ __launch_bounds__(256, 2)
void tgemm(const float* __restrict__ A, int lda,
           const float* __restrict__ B, int ldb,
           float* __restrict__ C, int ldc,
           int M, int N, int K,
           const float* __restrict__ bias)
{
    extern __shared__ unsigned dsm[];

    const int tx   = threadIdx.x;
    const int wid  = tx >> 5;
    const int lane = tx & 31;
    const int warp_m = wid >> 2;
    const int warp_n = wid & 3;
    const int bm = blockIdx.y * 128;
    const int bn = blockIdx.x * 128;
    const int Ksub = K / SK;
    const int kb   = Ksub * blockIdx.z;

    const int a_m  = tx >> 3;
    const int a_kv = tx & 7;
    const int b_q  = tx & 31;

    float acc[4][4][4] = {};

    float4 ar[4];
    float4 br0[2], br1[2];

    auto load_stage = [&](int k0){
        #pragma unroll
        for (int it = 0; it < 4; it++){
            int m = a_m + 32*it;
            if (MODE == 4){
                int mg = bm + m;
                int gb = mg / (NP*NP);
                int p  = mg % (NP*NP);
                int gi = p / NP, gj = p % NP;
                int k  = k0 + a_kv*4;
                int c  = k >> 10;
                int rem = k & 1023;
                int hh = rem >> 5, ww = rem & 31;
                size_t off = ((size_t)(gb*3 + c) * IMG + (gi*PS + hh)) * IMG + gj*PS + ww;
                ar[it] = *(const float4*)(A + off);
            } else {
                ar[it] = *(const float4*)(A + (size_t)(bm + m) * lda + k0 + a_kv*4);
            }
        }
        #pragma unroll
        for (int it = 0; it < 2; it++){
            int krow = (wid << 1) + (it << 4);
            br0[it] = *(const float4*)(B + (size_t)(k0 + krow    ) * ldb + bn + b_q*4);
            br1[it] = *(const float4*)(B + (size_t)(k0 + krow + 1) * ldb + bn + b_q*4);
        }
    };

    auto store_stage = [&](int buf){
        unsigned* sAh = dsm + buf*STAGEU;
        unsigned* sAl = sAh + 16*ASTRIDE;
        unsigned* sBh = sAh + 32*ASTRIDE;
        #pragma unroll
        for (int it = 0; it < 4; it++){
            int m   = a_m + 32*it;
            int ks  = a_kv >> 2;
            int kp0 = (a_kv & 3) * 2;            // k-pair idx within k16: 0,2,4,6
            int g   = (m >> 4)*2 + ks;
            int reg = ((m & 15) >> 3) + ((kp0 & 4) ? 2 : 0);
            int lane0 = (m & 7)*4 + (kp0 & 3);
            unsigned* baseA = sAh + g*ASTRIDE;
            unsigned* baseAl = sAl + g*ASTRIDE;
            unsigned uh, ul;
            hilo_pack(ar[it].x, ar[it].y, uh, ul);
            baseA[lane0*4 + reg]  = uh;  baseAl[lane0*4 + reg]  = ul;
            hilo_pack(ar[it].z, ar[it].w, uh, ul);
            baseA[(lane0+1)*4 + reg] = uh;  baseAl[(lane0+1)*4 + reg] = ul;
        }
        #pragma unroll
        for (int it = 0; it < 2; it++){
            int reg = (wid >> 2) & 1;
            int w3  = wid & 3;
            const float* r0 = (const float*)&br0[it];
            const float* r1 = (const float*)&br1[it];
            #pragma unroll
            for (int j = 0; j < 4; j++){
                int n  = b_q*4 + j;
                int g  = (n >> 3)*2 + it;
                int s  = (n >> 3) & 7;
                int ln = (((n & 7)*4 + w3) ^ s);
                sBh[g*BSTRIDE + ln*2 + reg] = h_pack(r0[j], r1[j]);
            }
        }
    };

    auto compute = [&](int buf){
        unsigned* sAh = dsm + buf*STAGEU;
        unsigned* sAl = sAh + 16*ASTRIDE;
        unsigned* sBh = sAh + 32*ASTRIDE;
        #pragma unroll
        for (int ks = 0; ks < 2; ks++){
            unsigned ah[4][4], al[4][4];
            unsigned bh[4][2];
            #pragma unroll
            for (int mt = 0; mt < 4; mt++){
                int g = (warp_m*4 + mt)*2 + ks;
                uint4 vh = *(const uint4*)(sAh + g*ASTRIDE + lane*4);
                uint4 vl = *(const uint4*)(sAl + g*ASTRIDE + lane*4);
                ah[mt][0] = vh.x; ah[mt][1] = vh.y; ah[mt][2] = vh.z; ah[mt][3] = vh.w;
                al[mt][0] = vl.x; al[mt][1] = vl.y; al[mt][2] = vl.z; al[mt][3] = vl.w;
            }
            #pragma unroll
            for (int nt = 0; nt < 4; nt++){
                int ntile = warp_n*4 + nt;
                int g  = ntile*2 + ks;
                int ln = lane ^ (ntile & 7);
                uint2 vb = *(const uint2*)(sBh + g*BSTRIDE + ln*2);
                bh[nt][0] = vb.x; bh[nt][1] = vb.y;
            }
            #pragma unroll
            for (int mt = 0; mt < 4; mt++)
                #pragma unroll
                for (int nt = 0; nt < 4; nt++){
                    mma_f16(acc[mt][nt], al[mt], bh[nt]);
                    mma_f16(acc[mt][nt], ah[mt], bh[nt]);
                }
        }
    };

    load_stage(kb);
    store_stage(0);
    __syncthreads();

    const int NS = Ksub / 32;
    for (int kt = 0; kt < NS; kt++){
        if (kt + 1 < NS) load_stage(kb + (kt + 1) * 32);
        compute(kt & 1);
        if (kt + 1 < NS){
            store_stage((kt + 1) & 1);
            __syncthreads();
        }
    }

    // ---- epilogue ----
    #pragma unroll
    for (int mt = 0; mt < 4; mt++){
        int r0 = bm + warp_m*64 + mt*16 + (lane >> 2);
        #pragma unroll
        for (int half = 0; half < 2; half++){
            int row = r0 + half*8;
            if (SK > 1){
                float* cp = C + ((size_t)blockIdx.z * M + row) * ldc
                              + bn + warp_n*32 + ((lane & 3) << 1);
                #pragma unroll
                for (int nt = 0; nt < 4; nt++){
                    float2 o;
                    o.x = acc[mt][nt][half*2 + 0];
                    o.y = acc[mt][nt][half*2 + 1];
                    *(float2*)(cp + nt*8) = o;
                }
                continue;
            }
            int orow = row;
            int tpos = 0;
            if (MODE == 4){
                int b = row / (NP*NP);
                int p = row % (NP*NP);
                tpos = p + 1;
                orow = b * NTOK + tpos;
            }
            #pragma unroll
            for (int nt = 0; nt < 4; nt++){
                int c0 = bn + warp_n*32 + nt*8 + ((lane & 3) << 1);
                float v0 = acc[mt][nt][half*2 + 0];
                float v1 = acc[mt][nt][half*2 + 1];
                if (MODE >= 2){ v0 += bias[c0]; v1 += bias[c0+1]; }
                if (MODE == 2){ v0 = gelu_exact(v0); v1 = gelu_exact(v1); }
                if (MODE == 4){
                    float fac = expf(-(float)c0 * 0.03597789207803285f);
                    float ang = (float)tpos * fac;
                    float s, c;
                    sincosf(ang, &s, &c);
                    v0 += s; v1 += c;
                }
                float* cp = C + (size_t)orow * ldc + c0;
                if (MODE == 3){
                    float2 old = *(const float2*)cp;
                    v0 += old.x; v1 += old.y;
                }
                float2 o; o.x = v0; o.y = v1;
                *(float2*)cp = o;
            }
        }
    }
}

// ---- combine kernel for patch-embed split-K ----
__global__ __launch_bounds__(256)
void combine_embed(const float* __restrict__ part, const float* __restrict__ bias,
                   float* __restrict__ x){
    int i = blockIdx.x * 256 + threadIdx.x;     // over PROWS*HID/2
    int c0  = (i * 2) % HID;
    int row = (i * 2) / HID;
    float2 s = make_float2(0.f, 0.f);
    #pragma unroll
    for (int z = 0; z < 4; z++){
        float2 v = *(const float2*)(part + ((size_t)z * PROWS + row) * HID + c0);
        s.x += v.x; s.y += v.y;
    }
    int b = row / (NP*NP);
    int p = row % (NP*NP);
    int tpos = p + 1;
    float fac = expf(-(float)c0 * 0.03597789207803285f);
    float sv, cv;
    sincosf((float)tpos * fac, &sv, &cv);
    s.x += bias[c0]   + sv;
    s.y += bias[c0+1] + cv;
    *(float2*)(x + ((size_t)(b * NTOK + tpos)) * HID + c0) = s;
}

// ---------------- SIMT GEMM (small head GEMM: +bias) ----------------
__global__ __launch_bounds__(256)
void gemm64(const float* __restrict__ A, int lda,
            const float* __restrict__ B, int ldb,
            float* __restrict__ C, int ldc,
            int M, int N, int K,
            const float* __restrict__ bias)
{
    __shared__ float As[16][64];
    __shared__ float Bs[16][68];

    const int tx = threadIdx.x;
    const int bm = blockIdx.y * 64;
    const int bn = blockIdx.x * 64;

    const int am  = tx >> 2;
    const int ak  = (tx & 3) << 2;
    const int bk  = tx >> 4;
    const int bnn = (tx & 15) << 2;
    const int tm  = (tx >> 4) << 2;
    const int tn  = (tx & 15) << 2;

    const int arow = bm + am;

    float acc[4][4];
    #pragma unroll
    for (int i=0;i<4;i++)
        #pragma unroll
        for (int j=0;j<4;j++) acc[i][j] = 0.f;

    for (int k0 = 0; k0 < K; k0 += 16){
        float4 av = make_float4(0.f,0.f,0.f,0.f);
        if (arow < M)
            av = *(const float4*)(A + (size_t)arow * lda + k0 + ak);
        As[ak+0][am] = av.x; As[ak+1][am] = av.y;
        As[ak+2][am] = av.z; As[ak+3][am] = av.w;

        float4 bv = make_float4(0.f,0.f,0.f,0.f);
        if (bn + bnn < N)
            bv = *(const float4*)(B + (size_t)(k0 + bk) * ldb + bn + bnn);
        *(float4*)&Bs[bk][bnn] = bv;

        __syncthreads();
        #pragma unroll
        for (int kk = 0; kk < 16; kk++){
            float4 a = *(const float4*)&As[kk][tm];
            float4 b = *(const float4*)&Bs[kk][tn];
            acc[0][0] += a.x*b.x; acc[0][1] += a.x*b.y; acc[0][2] += a.x*b.z; acc[0][3] += a.x*b.w;
            acc[1][0] += a.y*b.x; acc[1][1] += a.y*b.y; acc[1][2] += a.y*b.z; acc[1][3] += a.y*b.w;
            acc[2][0] += a.z*b.x; acc[2][1] += a.z*b.y; acc[2][2] += a.z*b.z; acc[2][3] += a.z*b.w;
            acc[3][0] += a.w*b.x; acc[3][1] += a.w*b.y; acc[3][2] += a.w*b.z; acc[3][3] += a.w*b.w;
        }
        __syncthreads();
    }

    #pragma unroll
    for (int i=0;i<4;i++){
        int row = bm + tm + i;
        if (row >= M) continue;
        #pragma unroll
        for (int j=0;j<4;j++){
            int col = bn + tn + j;
            if (col >= N) continue;
            C[(size_t)row * ldc + col] = acc[i][j] + bias[col];
        }
    }
}

// ---------------- CLS token init ----------------
__global__ void cls_init_kernel(const float* __restrict__ cls, float* __restrict__ x){
    int b = blockIdx.x, c = threadIdx.x;
    x[(size_t)b * NTOK * HID + c] = cls[c] + ((c & 1) ? 1.0f : 0.0f);
}

// ---------------- CSR build ----------------
__global__ void build_csr_kernel(const int* __restrict__ edge_index, int E){
    __shared__ int s_src[EMAX], s_dst[EMAX], cnt[NTOK];
    int t = threadIdx.x;
    for (int e = t; e < E; e += 64){
        s_src[e] = edge_index[e];
        s_dst[e] = edge_index[E + e];
    }
    __syncthreads();
    if (t < NTOK){
        int c = 1;
        for (int e = 0; e < E; e++) if (s_dst[e] == t) c++;
        cnt[t] = c;
    }
    __syncthreads();
    if (t == 0){
        int s = 0;
        for (int n = 0; n < NTOK; n++){ g_csr_ptr[n] = s; s += cnt[n]; }
        g_csr_ptr[NTOK] = s;
    }
    __syncthreads();
    if (t < NTOK){
        int pos = g_csr_ptr[t];
        for (int e = 0; e < E; e++) if (s_dst[e] == t) g_csr_src[pos++] = s_src[e];
        g_csr_src[pos++] = t;
    }
}

// ---------------- LayerNorm (warp-per-row, float out) ----------------
__global__ __launch_bounds__(256)
void ln_kernel(const float* __restrict__ x, float* __restrict__ y,
               const float* __restrict__ g, const float* __restrict__ b){
    int row  = blockIdx.x * 8 + (threadIdx.x >> 5);
    int lane = threadIdx.x & 31;
    const float* xr = x + (size_t)row * HID;
    float4 v0 = *(const float4*)(xr + lane*4);
    float4 v1 = *(const float4*)(xr + 128 + lane*4);
    float s = v0.x+v0.y+v0.z+v0.w + v1.x+v1.y+v1.z+v1.w;
    float mu = warpSum(s) * (1.0f / HID);
    float d0x=v0.x-mu, d0y=v0.y-mu, d0z=v0.z-mu, d0w=v0.w-mu;
    float d1x=v1.x-mu, d1y=v1.y-mu, d1z=v1.z-mu, d1w=v1.w-mu;
    float q = d0x*d0x+d0y*d0y+d0z*d0z+d0w*d0w + d1x*d1x+d1y*d1y+d1z*d1z+d1w*d1w;
    float var = warpSum(q) * (1.0f / HID);
    float inv = rsqrtf(var + 1e-5f);
    float4 g0 = *(const float4*)(g + lane*4);
    float4 g1 = *(const float4*)(g + 128 + lane*4);
    float4 b0 = *(const float4*)(b + lane*4);
    float4 b1 = *(const float4*)(b + 128 + lane*4);
    float* yr = y + (size_t)row * HID;
    float4 o0, o1;
    o0.x = d0x*inv*g0.x + b0.x; o0.y = d0y*inv*g0.y + b0.y;
    o0.z = d0z*inv*g0.z + b0.z; o0.w = d0w*inv*g0.w + b0.w;
    o1.x = d1x*inv*g1.x + b1.x; o1.y = d1y*inv*g1.y + b1.y;
    o1.z = d1z*inv*g1.z + b1.z; o1.w = d1w*inv*g1.w + b1.w;
    *(float4*)(yr + lane*4) = o0;
    *(float4*)(yr + 128 + lane*4) = o1;
}

// ---------------- per-head attention logit dots ----------------
__global__ __launch_bounds__(256)
void att_logits_kernel(const float* __restrict__ h,
                       const float* __restrict__ att_src,
                       const float* __restrict__ att_dst,
                       float* __restrict__ als, float* __restrict__ ald){
    int row = blockIdx.x;
    int w = threadIdx.x >> 5, lane = threadIdx.x & 31;
    float hv = h[(size_t)row * HID + w * DH + lane];
    float vs = warpSum(hv * att_src[w * DH + lane]);
    float vd = warpSum(hv * att_dst[w * DH + lane]);
    if (lane == 0){
        als[row * HEADS + w] = vs;
        ald[row * HEADS + w] = vd;
    }
}

// ---- fused: edge softmax + GAT aggregation + bias + residual + LN2 ----
__global__ __launch_bounds__(256)
void gat_fused_kernel(const float* __restrict__ h,
                      const float* __restrict__ als, const float* __restrict__ ald,
                      const float* __restrict__ bias, float* __restrict__ x,
                      float* __restrict__ y,
                      const float* __restrict__ g2, const float* __restrict__ b2){
    __shared__ float alpha_s[HEADS][64];
    __shared__ float sm[9];
    int b = blockIdx.x / NTOK, n = blockIdx.x % NTOK;
    int c = threadIdx.x;
    int head = c >> 5, lane = c & 31;
    int base = g_csr_ptr[n], deg = g_csr_ptr[n+1] - base;

    {
        float aldv = ald[(size_t)(b * NTOK + n) * HEADS + head];
        float m = -1e30f;
        for (int p = lane; p < deg; p += 32){
            int src = g_csr_src[base + p];
            float e = als[(size_t)(b * NTOK + src) * HEADS + head] + aldv;
            e = (e > 0.f) ? e : 0.2f * e;
            alpha_s[head][p] = e;
            m = fmaxf(m, e);
        }
        m = warpMax(m);
        float s = 0.f;
        for (int p = lane; p < deg; p += 32){
            float ex = expf(alpha_s[head][p] - m);
            alpha_s[head][p] = ex;
            s += ex;
        }
        s = warpSum(s);
        float inv = 1.0f / (s + 1e-16f);
        for (int p = lane; p < deg; p += 32)
            alpha_s[head][p] *= inv;
    }
    __syncthreads();

    float acc = 0.f;
    for (int p = 0; p < deg; p++){
        int src = g_csr_src[base + p];
        acc += alpha_s[head][p] * h[(size_t)(b * NTOK + src) * HID + c];
    }
    size_t idx = (size_t)(b * NTOK + n) * HID + c;
    float v = x[idx] + acc + bias[c];
    x[idx] = v;

    float mu = blockSum(v, sm) * (1.0f / HID);
    float d = v - mu;
    float var = blockSum(d * d, sm) * (1.0f / HID);
    float inv = rsqrtf(var + 1e-5f);
    y[idx] = d * inv * g2[c] + b2[c];
}

// ---------------- final row softmax ----------------
__global__ __launch_bounds__(256)
void softmax_kernel(const float* __restrict__ logits, float* __restrict__ out){
    __shared__ float sm[9];
    int row = blockIdx.x, t = threadIdx.x;
    float v[4];
    float m = -1e30f;
    #pragma unroll
    for (int k = 0; k < 4; k++){
        int c = t + k * 256;
        v[k] = (c < OUTD) ? logits[(size_t)row * OUTD + c] : -1e30f;
        m = fmaxf(m, v[k]);
    }
    m = blockMax(m, sm);
    float s = 0.f;
    #pragma unroll
    for (int k = 0; k < 4; k++){
        v[k] = expf(v[k] - m);
        int c = t + k * 256;
        if (c < OUTD) s += v[k];
    }
    s = blockSum(s, sm);
    float inv = 1.0f / s;
    #pragma unroll
    for (int k = 0; k < 4; k++){
        int c = t + k * 256;
        if (c < OUTD) out[(size_t)row * OUTD + c] = v[k] * inv;
    }
}

// ---------------- host launch ----------------
extern "C" void kernel_launch(void* const* d_in, const int* in_sizes, int n_in,
                              void* d_out, int out_size)
{
    const float* images  = (const float*)d_in[0];
    const int*   eidx    = (const int*)  d_in[1];
    const float* Wmap    = (const float*)d_in[2];
    const float* bmap    = (const float*)d_in[3];
    const float* cls_tok = (const float*)d_in[4];
    const float* Wgat    = (const float*)d_in[5];
    const float* att_src = (const float*)d_in[6];
    const float* att_dst = (const float*)d_in[7];
    const float* bgat    = (const float*)d_in[8];
    const float* ln1_g   = (const float*)d_in[9];
    const float* ln1_b   = (const float*)d_in[10];
    const float* ln2_g   = (const float*)d_in[11];
    const float* ln2_b   = (const float*)d_in[12];
    const float* W1      = (const float*)d_in[13];
    const float* b1      = (const float*)d_in[14];
    const float* W2      = (const float*)d_in[15];
    const float* b2      = (const float*)d_in[16];
    const float* Wout    = (const float*)d_in[17];
    const float* bout    = (const float*)d_in[18];

    int E = in_sizes[1] / 2;

    float *x, *y, *h, *mlp, *part, *als, *ald, *logits;
    cudaGetSymbolAddress((void**)&x,      g_x);
    cudaGetSymbolAddress((void**)&y,      g_y);
    cudaGetSymbolAddress((void**)&h,      g_h);
    cudaGetSymbolAddress((void**)&mlp,    g_mlp);
    cudaGetSymbolAddress((void**)&part,   g_part);
    cudaGetSymbolAddress((void**)&als,    g_als);
    cudaGetSymbolAddress((void**)&ald,    g_ald);
    cudaGetSymbolAddress((void**)&logits, g_logits);

    cudaFuncSetAttribute((const void*)tgemm<0,1>, cudaFuncAttributeMaxDynamicSharedMemorySize, TG_SMEM);
    cudaFuncSetAttribute((const void*)tgemm<2,1>, cudaFuncAttributeMaxDynamicSharedMemorySize, TG_SMEM);
    cudaFuncSetAttribute((const void*)tgemm<3,1>, cudaFuncAttributeMaxDynamicSharedMemorySize, TG_SMEM);
    cudaFuncSetAttribute((const void*)tgemm<4,4>, cudaFuncAttributeMaxDynamicSharedMemorySize, TG_SMEM);

    // patch embed: split-K=4 into partials, then combine(+bias+posemb+remap)
    tgemm<4,4><<<dim3(HID/128, PROWS/128, 4), 256, TG_SMEM>>>(
        images, 0, Wmap, HID, part, HID, PROWS, HID, INPUTD, nullptr);
    combine_embed<<<PROWS*HID/512, 256>>>(part, bmap, x);
    cls_init_kernel<<<BATCH, HID>>>(cls_tok, x);
    build_csr_kernel<<<1, 64>>>(eidx, E);

    for (int l = 0; l < 4; l++){
        ln_kernel<<<ROWS/8, 256>>>(x, y, ln1_g + l*HID, ln1_b + l*HID);
        tgemm<0,1><<<dim3(HID/128, ROWS/128), 256, TG_SMEM>>>(
            y, HID, Wgat + (size_t)l*HID*HID, HID,
            h, HID, ROWS, HID, HID, nullptr);
        att_logits_kernel<<<ROWS, 256>>>(h, att_src + l*HID, att_dst + l*HID, als, ald);
        gat_fused_kernel<<<ROWS, 256>>>(h, als, ald, bgat + l*HID, x, y,
                                        ln2_g + l*HID, ln2_b + l*HID);

        tgemm<2,1><<<dim3(MLPD/128, ROWS/128), 256, TG_SMEM>>>(
            y, HID, W1 + (size_t)l*HID*MLPD, MLPD,
            mlp, MLPD, ROWS, MLPD, HID, b1 + l*MLPD);
        tgemm<3,1><<<dim3(HID/128, ROWS/128), 256, TG_SMEM>>>(
            mlp, MLPD, W2 + (size_t)l*MLPD*HID, HID,
            x, HID, ROWS, HID, MLPD, b2 + l*HID);
    }

    gemm64<<<dim3((OUTD+63)/64, BATCH/64), 256>>>(x, NTOK*HID, Wout, OUTD,
                                                  logits, OUTD, BATCH, OUTD, HID, bout);
    softmax_kernel<<<BATCH, 256>>>(logits, (float*)d_out);
    (void)n_in; (void)out_size;
}

// round 17
// speedup vs baseline: 1.1096x; 1.0245x over previous
#include <cuda_runtime.h>
#include <cuda_fp16.h>
#include <cstdint>
#include <cstddef>

// ---------------- problem constants ----------------
#define BATCH   256
#define NTOK    50
#define NP      7
#define HID     256
#define HEADS   8
#define DH      32
#define MLPD    1024
#define OUTD    1000
#define PS      32
#define IMG     224
#define INPUTD  3072
#define ROWS    (BATCH*NTOK)      // 12800
#define PROWS   (BATCH*NP*NP)     // 12544
#define EMAX    512

// smem layout strides (u32)
#define ASTRIDE 132
#define BSTRIDE 66
#define STAGEU  (16*ASTRIDE*2 + 32*BSTRIDE)
#define TG_SMEM (2*STAGEU*4)

// ---------------- device scratch ----------------
__device__ float    g_x[ROWS*HID];
__device__ float    g_h[ROWS*HID];
__device__ float    g_part[4*PROWS*HID];
__device__ float    g_als[ROWS*HEADS];
__device__ float    g_ald[ROWS*HEADS];
__device__ float    g_logits[BATCH*OUTD];
__device__ int      g_csr_ptr[NTOK+1];
__device__ int      g_csr_src[1024];
// interleaved hi/lo fp16 activations: u32[row*ld + c] (c even: h-pair, c odd slot: l-pair)
__device__ unsigned g_y2[ROWS*HID];
__device__ unsigned g_mlp2[ROWS*MLPD];
// hi-only fp16 weights, k-pair packed: [l][K/2][N] u32
__device__ unsigned g_WgatH[4*(HID/2)*HID];
__device__ unsigned g_W1H[4*(HID/2)*MLPD];
__device__ unsigned g_W2H[4*(MLPD/2)*HID];

// ---------------- helpers ----------------
__device__ __forceinline__ float warpSum(float v){
    #pragma unroll
    for (int o=16;o;o>>=1) v += __shfl_xor_sync(0xffffffffu, v, o);
    return v;
}
__device__ __forceinline__ float warpMax(float v){
    #pragma unroll
    for (int o=16;o;o>>=1) v = fmaxf(v, __shfl_xor_sync(0xffffffffu, v, o));
    return v;
}
__device__ __forceinline__ float blockSum(float v, float* sm){
    int lane = threadIdx.x & 31, w = threadIdx.x >> 5;
    v = warpSum(v);
    if (lane == 0) sm[w] = v;
    __syncthreads();
    if (threadIdx.x == 0){
        float s = 0.f;
        for (int i = 0; i < 8; i++) s += sm[i];
        sm[8] = s;
    }
    __syncthreads();
    return sm[8];
}
__device__ __forceinline__ float blockMax(float v, float* sm){
    int lane = threadIdx.x & 31, w = threadIdx.x >> 5;
    v = warpMax(v);
    if (lane == 0) sm[w] = v;
    __syncthreads();
    if (threadIdx.x == 0){
        float s = sm[0];
        for (int i = 1; i < 8; i++) s = fmaxf(s, sm[i]);
        sm[8] = s;
    }
    __syncthreads();
    return sm[8];
}
__device__ __forceinline__ float gelu_exact(float v){
    return 0.5f * v * (1.0f + erff(v * 0.7071067811865475f));
}
__device__ __forceinline__ void hilo_pack(float x, float y, unsigned& uh, unsigned& ul){
    __half hx = __float2half_rn(x);
    __half hy = __float2half_rn(y);
    __half lx = __float2half_rn(x - __half2float(hx));
    __half ly = __float2half_rn(y - __half2float(hy));
    __half2 th = __halves2half2(hx, hy);
    __half2 tl = __halves2half2(lx, ly);
    uh = *reinterpret_cast<unsigned*>(&th);
    ul = *reinterpret_cast<unsigned*>(&tl);
}
__device__ __forceinline__ unsigned h_pack(float x, float y){
    __half2 t = __halves2half2(__float2half_rn(x), __float2half_rn(y));
    return *reinterpret_cast<unsigned*>(&t);
}
__device__ __forceinline__ void mma_f16(float* d, const unsigned* a, const unsigned* b){
    asm volatile(
        "mma.sync.aligned.m16n8k16.row.col.f32.f16.f16.f32 "
        "{%0,%1,%2,%3}, {%4,%5,%6,%7}, {%8,%9}, {%0,%1,%2,%3};\n"
        : "+f"(d[0]), "+f"(d[1]), "+f"(d[2]), "+f"(d[3])
        : "r"(a[0]), "r"(a[1]), "r"(a[2]), "r"(a[3]), "r"(b[0]), "r"(b[1]));
}

// ---------------- weight pre-conversion: hi fp16, k-pair packed ----------------
__global__ void cvt_w_hi(const float* __restrict__ W, unsigned* __restrict__ WH,
                         int K, int N, int L){
    long idx = (long)blockIdx.x * blockDim.x + threadIdx.x;
    long total = (long)L * (K/2) * N;
    if (idx < total){
        int n  = idx % N;
        long t = idx / N;
        int kp = t % (K/2);
        int l  = t / (K/2);
        const float* Wl = W + (size_t)l * K * N;
        WH[idx] = h_pack(Wl[(size_t)(2*kp) * N + n], Wl[(size_t)(2*kp+1) * N + n]);
    }
}

// =============================================================
// tgemm_pre: interleaved pre-converted operands — ZERO cvt in the loop.
// A: u32[row*lda + c] with quads {h01,l01,h23,l23}; B: hi k-pair [K/2][N] u32.
// 2xFP16 D = (Ah+Al)@Bh. 128x128x32 tile, double-buffered, 2 CTAs/SM.
// MODE 0: C=A@B (f32) | MODE 2: gelu(+bias) -> out2 interleaved | MODE 3: C+=A@B+bias
// =============================================================
template<int MODE>
__global__ __launch_bounds__(256, 2)
void tgemm_pre(const unsigned* __restrict__ A, int lda,
               const unsigned* __restrict__ BH,
               float* __restrict__ C, int ldc,
               int M, int N, int K,
               const float* __restrict__ bias,
               unsigned* __restrict__ out2)
{
    extern __shared__ unsigned dsm[];

    const int tx   = threadIdx.x;
    const int wid  = tx >> 5;
    const int lane = tx & 31;
    const int warp_m = wid >> 2;
    const int warp_n = wid & 3;
    const int bm = blockIdx.y * 128;
    const int bn = blockIdx.x * 128;

    const int a_m  = tx >> 3;
    const int a_kv = tx & 7;
    const int b_q  = tx & 31;

    float acc[4][4][4] = {};

    uint4 av[4], bv[2];

    auto load_stage = [&](int k0){
        #pragma unroll
        for (int it = 0; it < 4; it++){
            size_t idx = (size_t)(bm + a_m + 32*it) * lda + k0 + a_kv*4;
            av[it] = *(const uint4*)(A + idx);
        }
        #pragma unroll
        for (int it = 0; it < 2; it++){
            int kp = (k0 >> 1) + wid + (it << 3);
            bv[it] = *(const uint4*)(BH + (size_t)kp * N + bn + b_q*4);
        }
    };

    auto store_stage = [&](int buf){
        unsigned* sAh = dsm + buf*STAGEU;
        unsigned* sAl = sAh + 16*ASTRIDE;
        unsigned* sBh = sAh + 32*ASTRIDE;
        #pragma unroll
        for (int it = 0; it < 4; it++){
            int m   = a_m + 32*it;
            int ks  = a_kv >> 2;
            int kp0 = (a_kv & 3) * 2;
            int g   = (m >> 4)*2 + ks;
            int reg = ((m & 15) >> 3) + ((kp0 & 4) ? 2 : 0);
            int lane0 = (m & 7)*4 + (kp0 & 3);
            unsigned* bAh = sAh + g*ASTRIDE;
            unsigned* bAl = sAl + g*ASTRIDE;
            bAh[lane0*4 + reg]     = av[it].x;   // h01
            bAl[lane0*4 + reg]     = av[it].y;   // l01
            bAh[(lane0+1)*4 + reg] = av[it].z;   // h23
            bAl[(lane0+1)*4 + reg] = av[it].w;   // l23
        }
        #pragma unroll
        for (int it = 0; it < 2; it++){
            int reg = (wid >> 2) & 1;
            int w3  = wid & 3;
            const unsigned* uc = (const unsigned*)&bv[it];
            #pragma unroll
            for (int j = 0; j < 4; j++){
                int n  = b_q*4 + j;
                int g  = (n >> 3)*2 + it;
                int s  = (n >> 3) & 7;
                int ln = (((n & 7)*4 + w3) ^ s);
                sBh[g*BSTRIDE + ln*2 + reg] = uc[j];
            }
        }
    };

    auto compute = [&](int buf){
        unsigned* sAh = dsm + buf*STAGEU;
        unsigned* sAl = sAh + 16*ASTRIDE;
        unsigned* sBh = sAh + 32*ASTRIDE;
        #pragma unroll
        for (int ks = 0; ks < 2; ks++){
            unsigned ah[4][4], al[4][4];
            unsigned bh[4][2];
            #pragma unroll
            for (int mt = 0; mt < 4; mt++){
                int g = (warp_m*4 + mt)*2 + ks;
                uint4 vh = *(const uint4*)(sAh + g*ASTRIDE + lane*4);
                uint4 vl = *(const uint4*)(sAl + g*ASTRIDE + lane*4);
                ah[mt][0] = vh.x; ah[mt][1] = vh.y; ah[mt][2] = vh.z; ah[mt][3] = vh.w;
                al[mt][0] = vl.x; al[mt][1] = vl.y; al[mt][2] = vl.z; al[mt][3] = vl.w;
            }
            #pragma unroll
            for (int nt = 0; nt < 4; nt++){
                int ntile = warp_n*4 + nt;
                int g  = ntile*2 + ks;
                int ln = lane ^ (ntile & 7);
                uint2 vb = *(const uint2*)(sBh + g*BSTRIDE + ln*2);
                bh[nt][0] = vb.x; bh[nt][1] = vb.y;
            }
            #pragma unroll
            for (int mt = 0; mt < 4; mt++)
                #pragma unroll
                for (int nt = 0; nt < 4; nt++){
                    mma_f16(acc[mt][nt], al[mt], bh[nt]);
                    mma_f16(acc[mt][nt], ah[mt], bh[nt]);
                }
        }
    };

    load_stage(0);
    store_stage(0);
    __syncthreads();

    const int NS = K / 32;
    for (int kt = 0; kt < NS; kt++){
        if (kt + 1 < NS) load_stage((kt + 1) * 32);
        compute(kt & 1);
        if (kt + 1 < NS){
            store_stage((kt + 1) & 1);
            __syncthreads();
        }
    }

    // ---- epilogue ----
    #pragma unroll
    for (int mt = 0; mt < 4; mt++){
        int r0 = bm + warp_m*64 + mt*16 + (lane >> 2);
        #pragma unroll
        for (int half = 0; half < 2; half++){
            int row = r0 + half*8;
            #pragma unroll
            for (int nt = 0; nt < 4; nt++){
                int c0 = bn + warp_n*32 + nt*8 + ((lane & 3) << 1);
                float v0 = acc[mt][nt][half*2 + 0];
                float v1 = acc[mt][nt][half*2 + 1];
                if (MODE >= 2){ v0 += bias[c0]; v1 += bias[c0+1]; }
                if (MODE == 2){
                    v0 = gelu_exact(v0); v1 = gelu_exact(v1);
                    unsigned uh, ul;
                    hilo_pack(v0, v1, uh, ul);
                    *(uint2*)(out2 + (size_t)row * ldc + c0) = make_uint2(uh, ul);
                    continue;
                }
                float* cp = C + (size_t)row * ldc + c0;
                if (MODE == 3){
                    float2 old = *(const float2*)cp;
                    v0 += old.x; v1 += old.y;
                }
                float2 o; o.x = v0; o.y = v1;
                *(float2*)cp = o;
            }
        }
    }
}

// =============================================================
// tgemm4: patch-embed, inline fp32 conversion, split-K (blockIdx.z), raw partials
// =============================================================
__global__ __launch_bounds__(256, 2)
void tgemm4(const float* __restrict__ A,
            const float* __restrict__ B, int ldb,
            float* __restrict__ C, int ldc,
            int M, int N, int K)
{
    extern __shared__ unsigned dsm[];

    const int tx   = threadIdx.x;
    const int wid  = tx >> 5;
    const int lane = tx & 31;
    const int warp_m = wid >> 2;
    const int warp_n = wid & 3;
    const int bm = blockIdx.y * 128;
    const int bn = blockIdx.x * 128;
    const int Ksub = K / 4;
    const int kb   = Ksub * blockIdx.z;

    const int a_m  = tx >> 3;
    const int a_kv = tx & 7;
    const int b_q  = tx & 31;

    float acc[4][4][4] = {};
    float4 ar[4];
    float4 br0[2], br1[2];

    auto load_stage = [&](int k0){
        #pragma unroll
        for (int it = 0; it < 4; it++){
            int mg = bm + a_m + 32*it;
            int gb = mg / (NP*NP);
            int p  = mg % (NP*NP);
            int gi = p / NP, gj = p % NP;
            int k  = k0 + a_kv*4;
            int c  = k >> 10;
            int rem = k & 1023;
            int hh = rem >> 5, ww = rem & 31;
            size_t off = ((size_t)(gb*3 + c) * IMG + (gi*PS + hh)) * IMG + gj*PS + ww;
            ar[it] = *(const float4*)(A + off);
        }
        #pragma unroll
        for (int it = 0; it < 2; it++){
            int krow = (wid << 1) + (it << 4);
            br0[it] = *(const float4*)(B + (size_t)(k0 + krow    ) * ldb + bn + b_q*4);
            br1[it] = *(const float4*)(B + (size_t)(k0 + krow + 1) * ldb + bn + b_q*4);
        }
    };

    auto store_stage = [&](int buf){
        unsigned* sAh = dsm + buf*STAGEU;
        unsigned* sAl = sAh + 16*ASTRIDE;
        unsigned* sBh = sAh + 32*ASTRIDE;
        #pragma unroll
        for (int it = 0; it < 4; it++){
            int m   = a_m + 32*it;
            int ks  = a_kv >> 2;
            int kp0 = (a_kv & 3) * 2;
            int g   = (m >> 4)*2 + ks;
            int reg = ((m & 15) >> 3) + ((kp0 & 4) ? 2 : 0);
            int lane0 = (m & 7)*4 + (kp0 & 3);
            unsigned* bAh = sAh + g*ASTRIDE;
            unsigned* bAl = sAl + g*ASTRIDE;
            unsigned uh, ul;
            hilo_pack(ar[it].x, ar[it].y, uh, ul);
            bAh[lane0*4 + reg]  = uh;  bAl[lane0*4 + reg]  = ul;
            hilo_pack(ar[it].z, ar[it].w, uh, ul);
            bAh[(lane0+1)*4 + reg] = uh;  bAl[(lane0+1)*4 + reg] = ul;
        }
        #pragma unroll
        for (int it = 0; it < 2; it++){
            int reg = (wid >> 2) & 1;
            int w3  = wid & 3;
            const float* r0 = (const float*)&br0[it];
            const float* r1 = (const float*)&br1[it];
            #pragma unroll
            for (int j = 0; j < 4; j++){
                int n  = b_q*4 + j;
                int g  = (n >> 3)*2 + it;
                int s  = (n >> 3) & 7;
                int ln = (((n & 7)*4 + w3) ^ s);
                sBh[g*BSTRIDE + ln*2 + reg] = h_pack(r0[j], r1[j]);
            }
        }
    };

    auto compute = [&](int buf){
        unsigned* sAh = dsm + buf*STAGEU;
        unsigned* sAl = sAh + 16*ASTRIDE;
        unsigned* sBh = sAh + 32*ASTRIDE;
        #pragma unroll
        for (int ks = 0; ks < 2; ks++){
            unsigned ah[4][4], al[4][4];
            unsigned bh[4][2];
            #pragma unroll
            for (int mt = 0; mt < 4; mt++){
                int g = (warp_m*4 + mt)*2 + ks;
                uint4 vh = *(const uint4*)(sAh + g*ASTRIDE + lane*4);
                uint4 vl = *(const uint4*)(sAl + g*ASTRIDE + lane*4);
                ah[mt][0] = vh.x; ah[mt][1] = vh.y; ah[mt][2] = vh.z; ah[mt][3] = vh.w;
                al[mt][0] = vl.x; al[mt][1] = vl.y; al[mt][2] = vl.z; al[mt][3] = vl.w;
            }
            #pragma unroll
            for (int nt = 0; nt < 4; nt++){
                int ntile = warp_n*4 + nt;
                int g  = ntile*2 + ks;
                int ln = lane ^ (ntile & 7);
                uint2 vb = *(const uint2*)(sBh + g*BSTRIDE + ln*2);
                bh[nt][0] = vb.x; bh[nt][1] = vb.y;
            }
            #pragma unroll
            for (int mt = 0; mt < 4; mt++)
                #pragma unroll
                for (int nt = 0; nt < 4; nt++){
                    mma_f16(acc[mt][nt], al[mt], bh[nt]);
                    mma_f16(acc[mt][nt], ah[mt], bh[nt]);
                }
        }
    };

    load_stage(kb);
    store_stage(0);
    __syncthreads();

    const int NS = Ksub / 32;
    for (int kt = 0; kt < NS; kt++){
        if (kt + 1 < NS) load_stage(kb + (kt + 1) * 32);
        compute(kt & 1);
        if (kt + 1 < NS){
            store_stage((kt + 1) & 1);
            __syncthreads();
        }
    }

    #pragma unroll
    for (int mt = 0; mt < 4; mt++){
        int r0 = bm + warp_m*64 + mt*16 + (lane >> 2);
        #pragma unroll
        for (int half = 0; half < 2; half++){
            int row = r0 + half*8;
            float* cp = C + ((size_t)blockIdx.z * M + row) * ldc
                          + bn + warp_n*32 + ((lane & 3) << 1);
            #pragma unroll
            for (int nt = 0; nt < 4; nt++){
                float2 o;
                o.x = acc[mt][nt][half*2 + 0];
                o.y = acc[mt][nt][half*2 + 1];
                *(float2*)(cp + nt*8) = o;
            }
        }
    }
}

// ---- combine kernel for patch-embed split-K ----
__global__ __launch_bounds__(256)
void combine_embed(const float* __restrict__ part, const float* __restrict__ bias,
                   float* __restrict__ x){
    int i = blockIdx.x * 256 + threadIdx.x;
    int c0  = (i * 2) % HID;
    int row = (i * 2) / HID;
    float2 s = make_float2(0.f, 0.f);
    #pragma unroll
    for (int z = 0; z < 4; z++){
        float2 v = *(const float2*)(part + ((size_t)z * PROWS + row) * HID + c0);
        s.x += v.x; s.y += v.y;
    }
    int b = row / (NP*NP);
    int p = row % (NP*NP);
    int tpos = p + 1;
    float fac = expf(-(float)c0 * 0.03597789207803285f);
    float sv, cv;
    sincosf((float)tpos * fac, &sv, &cv);
    s.x += bias[c0]   + sv;
    s.y += bias[c0+1] + cv;
    *(float2*)(x + ((size_t)(b * NTOK + tpos)) * HID + c0) = s;
}

// ---------------- SIMT GEMM (small head GEMM: +bias) ----------------
__global__ __launch_bounds__(256)
void gemm64(const float* __restrict__ A, int lda,
            const float* __restrict__ B, int ldb,
            float* __restrict__ C, int ldc,
            int M, int N, int K,
            const float* __restrict__ bias)
{
    __shared__ float As[16][64];
    __shared__ float Bs[16][68];

    const int tx = threadIdx.x;
    const int bm = blockIdx.y * 64;
    const int bn = blockIdx.x * 64;

    const int am  = tx >> 2;
    const int ak  = (tx & 3) << 2;
    const int bk  = tx >> 4;
    const int bnn = (tx & 15) << 2;
    const int tm  = (tx >> 4) << 2;
    const int tn  = (tx & 15) << 2;

    const int arow = bm + am;

    float acc[4][4];
    #pragma unroll
    for (int i=0;i<4;i++)
        #pragma unroll
        for (int j=0;j<4;j++) acc[i][j] = 0.f;

    for (int k0 = 0; k0 < K; k0 += 16){
        float4 av = make_float4(0.f,0.f,0.f,0.f);
        if (arow < M)
            av = *(const float4*)(A + (size_t)arow * lda + k0 + ak);
        As[ak+0][am] = av.x; As[ak+1][am] = av.y;
        As[ak+2][am] = av.z; As[ak+3][am] = av.w;

        float4 bv = make_float4(0.f,0.f,0.f,0.f);
        if (bn + bnn < N)
            bv = *(const float4*)(B + (size_t)(k0 + bk) * ldb + bn + bnn);
        *(float4*)&Bs[bk][bnn] = bv;

        __syncthreads();
        #pragma unroll
        for (int kk = 0; kk < 16; kk++){
            float4 a = *(const float4*)&As[kk][tm];
            float4 b = *(const float4*)&Bs[kk][tn];
            acc[0][0] += a.x*b.x; acc[0][1] += a.x*b.y; acc[0][2] += a.x*b.z; acc[0][3] += a.x*b.w;
            acc[1][0] += a.y*b.x; acc[1][1] += a.y*b.y; acc[1][2] += a.y*b.z; acc[1][3] += a.y*b.w;
            acc[2][0] += a.z*b.x; acc[2][1] += a.z*b.y; acc[2][2] += a.z*b.z; acc[2][3] += a.z*b.w;
            acc[3][0] += a.w*b.x; acc[3][1] += a.w*b.y; acc[3][2] += a.w*b.z; acc[3][3] += a.w*b.w;
        }
        __syncthreads();
    }

    #pragma unroll
    for (int i=0;i<4;i++){
        int row = bm + tm + i;
        if (row >= M) continue;
        #pragma unroll
        for (int j=0;j<4;j++){
            int col = bn + tn + j;
            if (col >= N) continue;
            C[(size_t)row * ldc + col] = acc[i][j] + bias[col];
        }
    }
}

// ---------------- CLS token init ----------------
__global__ void cls_init_kernel(const float* __restrict__ cls, float* __restrict__ x){
    int b = blockIdx.x, c = threadIdx.x;
    x[(size_t)b * NTOK * HID + c] = cls[c] + ((c & 1) ? 1.0f : 0.0f);
}

// ---------------- CSR build ----------------
__global__ void build_csr_kernel(const int* __restrict__ edge_index, int E){
    __shared__ int s_src[EMAX], s_dst[EMAX], cnt[NTOK];
    int t = threadIdx.x;
    for (int e = t; e < E; e += 64){
        s_src[e] = edge_index[e];
        s_dst[e] = edge_index[E + e];
    }
    __syncthreads();
    if (t < NTOK){
        int c = 1;
        for (int e = 0; e < E; e++) if (s_dst[e] == t) c++;
        cnt[t] = c;
    }
    __syncthreads();
    if (t == 0){
        int s = 0;
        for (int n = 0; n < NTOK; n++){ g_csr_ptr[n] = s; s += cnt[n]; }
        g_csr_ptr[NTOK] = s;
    }
    __syncthreads();
    if (t < NTOK){
        int pos = g_csr_ptr[t];
        for (int e = 0; e < E; e++) if (s_dst[e] == t) g_csr_src[pos++] = s_src[e];
        g_csr_src[pos++] = t;
    }
}

// ---------------- LayerNorm (warp-per-row) -> interleaved hi/lo ----------------
__global__ __launch_bounds__(256)
void ln_kernel(const float* __restrict__ x, unsigned* __restrict__ y2,
               const float* __restrict__ g, const float* __restrict__ b){
    int row  = blockIdx.x * 8 + (threadIdx.x >> 5);
    int lane = threadIdx.x & 31;
    const float* xr = x + (size_t)row * HID;
    float4 v0 = *(const float4*)(xr + lane*4);
    float4 v1 = *(const float4*)(xr + 128 + lane*4);
    float s = v0.x+v0.y+v0.z+v0.w + v1.x+v1.y+v1.z+v1.w;
    float mu = warpSum(s) * (1.0f / HID);
    float d0x=v0.x-mu, d0y=v0.y-mu, d0z=v0.z-mu, d0w=v0.w-mu;
    float d1x=v1.x-mu, d1y=v1.y-mu, d1z=v1.z-mu, d1w=v1.w-mu;
    float q = d0x*d0x+d0y*d0y+d0z*d0z+d0w*d0w + d1x*d1x+d1y*d1y+d1z*d1z+d1w*d1w;
    float var = warpSum(q) * (1.0f / HID);
    float inv = rsqrtf(var + 1e-5f);
    float4 g0 = *(const float4*)(g + lane*4);
    float4 g1 = *(const float4*)(g + 128 + lane*4);
    float4 b0 = *(const float4*)(b + lane*4);
    float4 b1 = *(const float4*)(b + 128 + lane*4);
    float o0x = d0x*inv*g0.x + b0.x, o0y = d0y*inv*g0.y + b0.y;
    float o0z = d0z*inv*g0.z + b0.z, o0w = d0w*inv*g0.w + b0.w;
    float o1x = d1x*inv*g1.x + b1.x, o1y = d1y*inv*g1.y + b1.y;
    float o1z = d1z*inv*g1.z + b1.z, o1w = d1w*inv*g1.w + b1.w;
    unsigned h0,l0,h1,l1,h2,l2,h3,l3;
    hilo_pack(o0x,o0y,h0,l0); hilo_pack(o0z,o0w,h1,l1);
    hilo_pack(o1x,o1y,h2,l2); hilo_pack(o1z,o1w,h3,l3);
    // interleaved quads {h01,l01,h23,l23}
    *(uint4*)(y2 + (size_t)row * HID + lane*4)       = make_uint4(h0,l0,h1,l1);
    *(uint4*)(y2 + (size_t)row * HID + 128 + lane*4) = make_uint4(h2,l2,h3,l3);
}

// ---------------- per-head attention logit dots ----------------
__global__ __launch_bounds__(256)
void att_logits_kernel(const float* __restrict__ h,
                       const float* __restrict__ att_src,
                       const float* __restrict__ att_dst,
                       float* __restrict__ als, float* __restrict__ ald){
    int row = blockIdx.x;
    int w = threadIdx.x >> 5, lane = threadIdx.x & 31;
    float hv = h[(size_t)row * HID + w * DH + lane];
    float vs = warpSum(hv * att_src[w * DH + lane]);
    float vd = warpSum(hv * att_dst[w * DH + lane]);
    if (lane == 0){
        als[row * HEADS + w] = vs;
        ald[row * HEADS + w] = vd;
    }
}

// ---- fused: edge softmax + GAT agg + bias + residual + LN2 -> interleaved ----
__global__ __launch_bounds__(256)
void gat_fused_kernel(const float* __restrict__ h,
                      const float* __restrict__ als, const float* __restrict__ ald,
                      const float* __restrict__ bias, float* __restrict__ x,
                      unsigned* __restrict__ y2,
                      const float* __restrict__ g2, const float* __restrict__ b2){
    __shared__ float alpha_s[HEADS][64];
    __shared__ float sm[9];
    __shared__ float vsh[HID];
    int b = blockIdx.x / NTOK, n = blockIdx.x % NTOK;
    int c = threadIdx.x;
    int head = c >> 5, lane = c & 31;
    int base = g_csr_ptr[n], deg = g_csr_ptr[n+1] - base;

    {
        float aldv = ald[(size_t)(b * NTOK + n) * HEADS + head];
        float m = -1e30f;
        for (int p = lane; p < deg; p += 32){
            int src = g_csr_src[base + p];
            float e = als[(size_t)(b * NTOK + src) * HEADS + head] + aldv;
            e = (e > 0.f) ? e : 0.2f * e;
            alpha_s[head][p] = e;
            m = fmaxf(m, e);
        }
        m = warpMax(m);
        float s = 0.f;
        for (int p = lane; p < deg; p += 32){
            float ex = expf(alpha_s[head][p] - m);
            alpha_s[head][p] = ex;
            s += ex;
        }
        s = warpSum(s);
        float inv = 1.0f / (s + 1e-16f);
        for (int p = lane; p < deg; p += 32)
            alpha_s[head][p] *= inv;
    }
    __syncthreads();

    float acc = 0.f;
    for (int p = 0; p < deg; p++){
        int src = g_csr_src[base + p];
        acc += alpha_s[head][p] * h[(size_t)(b * NTOK + src) * HID + c];
    }
    size_t idx = (size_t)(b * NTOK + n) * HID + c;
    float v = x[idx] + acc + bias[c];
    x[idx] = v;

    float mu = blockSum(v, sm) * (1.0f / HID);
    float d = v - mu;
    float var = blockSum(d * d, sm) * (1.0f / HID);
    float inv = rsqrtf(var + 1e-5f);
    float o = d * inv * g2[c] + b2[c];
    vsh[c] = o;
    __syncthreads();
    if ((c & 1) == 0){
        unsigned uh, ul;
        hilo_pack(vsh[c], vsh[c+1], uh, ul);
        *(uint2*)(y2 + (size_t)(b * NTOK + n) * HID + c) = make_uint2(uh, ul);
    }
}

// ---------------- final row softmax ----------------
__global__ __launch_bounds__(256)
void softmax_kernel(const float* __restrict__ logits, float* __restrict__ out){
    __shared__ float sm[9];
    int row = blockIdx.x, t = threadIdx.x;
    float v[4];
    float m = -1e30f;
    #pragma unroll
    for (int k = 0; k < 4; k++){
        int c = t + k * 256;
        v[k] = (c < OUTD) ? logits[(size_t)row * OUTD + c] : -1e30f;
        m = fmaxf(m, v[k]);
    }
    m = blockMax(m, sm);
    float s = 0.f;
    #pragma unroll
    for (int k = 0; k < 4; k++){
        v[k] = expf(v[k] - m);
        int c = t + k * 256;
        if (c < OUTD) s += v[k];
    }
    s = blockSum(s, sm);
    float inv = 1.0f / s;
    #pragma unroll
    for (int k = 0; k < 4; k++){
        int c = t + k * 256;
        if (c < OUTD) out[(size_t)row * OUTD + c] = v[k] * inv;
    }
}

// ---------------- host launch ----------------
extern "C" void kernel_launch(void* const* d_in, const int* in_sizes, int n_in,
                              void* d_out, int out_size)
{
    const float* images  = (const float*)d_in[0];
    const int*   eidx    = (const int*)  d_in[1];
    const float* Wmap    = (const float*)d_in[2];
    const float* bmap    = (const float*)d_in[3];
    const float* cls_tok = (const float*)d_in[4];
    const float* Wgat    = (const float*)d_in[5];
    const float* att_src = (const float*)d_in[6];
    const float* att_dst = (const float*)d_in[7];
    const float* bgat    = (const float*)d_in[8];
    const float* ln1_g   = (const float*)d_in[9];
    const float* ln1_b   = (const float*)d_in[10];
    const float* ln2_g   = (const float*)d_in[11];
    const float* ln2_b   = (const float*)d_in[12];
    const float* W1      = (const float*)d_in[13];
    const float* b1      = (const float*)d_in[14];
    const float* W2      = (const float*)d_in[15];
    const float* b2      = (const float*)d_in[16];
    const float* Wout    = (const float*)d_in[17];
    const float* bout    = (const float*)d_in[18];

    int E = in_sizes[1] / 2;

    float *x, *h, *part, *als, *ald, *logits;
    unsigned *y2, *mlp2, *WgatH, *W1H, *W2H;
    cudaGetSymbolAddress((void**)&x,      g_x);
    cudaGetSymbolAddress((void**)&h,      g_h);
    cudaGetSymbolAddress((void**)&part,   g_part);
    cudaGetSymbolAddress((void**)&als,    g_als);
    cudaGetSymbolAddress((void**)&ald,    g_ald);
    cudaGetSymbolAddress((void**)&logits, g_logits);
    cudaGetSymbolAddress((void**)&y2,     g_y2);
    cudaGetSymbolAddress((void**)&mlp2,   g_mlp2);
    cudaGetSymbolAddress((void**)&WgatH,  g_WgatH);
    cudaGetSymbolAddress((void**)&W1H,    g_W1H);
    cudaGetSymbolAddress((void**)&W2H,    g_W2H);

    cudaFuncSetAttribute((const void*)tgemm_pre<0>, cudaFuncAttributeMaxDynamicSharedMemorySize, TG_SMEM);
    cudaFuncSetAttribute((const void*)tgemm_pre<2>, cudaFuncAttributeMaxDynamicSharedMemorySize, TG_SMEM);
    cudaFuncSetAttribute((const void*)tgemm_pre<3>, cudaFuncAttributeMaxDynamicSharedMemorySize, TG_SMEM);
    cudaFuncSetAttribute((const void*)tgemm4,       cudaFuncAttributeMaxDynamicSharedMemorySize, TG_SMEM);

    // weight pre-conversion (hi fp16, k-pair packed)
    {
        long t;
        t = (long)4*(HID/2)*HID;
        cvt_w_hi<<<(unsigned)((t + 255)/256), 256>>>(Wgat, WgatH, HID, HID, 4);
        t = (long)4*(HID/2)*MLPD;
        cvt_w_hi<<<(unsigned)((t + 255)/256), 256>>>(W1, W1H, HID, MLPD, 4);
        t = (long)4*(MLPD/2)*HID;
        cvt_w_hi<<<(unsigned)((t + 255)/256), 256>>>(W2, W2H, MLPD, HID, 4);
    }

    // patch embed: split-K=4 + combine
    tgemm4<<<dim3(HID/128, PROWS/128, 4), 256, TG_SMEM>>>(
        images, Wmap, HID, part, HID, PROWS, HID, INPUTD);
    combine_embed<<<PROWS*HID/512, 256>>>(part, bmap, x);
    cls_init_kernel<<<BATCH, HID>>>(cls_tok, x);
    build_csr_kernel<<<1, 64>>>(eidx, E);

    for (int l = 0; l < 4; l++){
        ln_kernel<<<ROWS/8, 256>>>(x, y2, ln1_g + l*HID, ln1_b + l*HID);
        tgemm_pre<0><<<dim3(HID/128, ROWS/128), 256, TG_SMEM>>>(
            y2, HID, WgatH + (size_t)l*(HID/2)*HID,
            h, HID, ROWS, HID, HID, nullptr, nullptr);
        att_logits_kernel<<<ROWS, 256>>>(h, att_src + l*HID, att_dst + l*HID, als, ald);
        gat_fused_kernel<<<ROWS, 256>>>(h, als, ald, bgat + l*HID, x, y2,
                                        ln2_g + l*HID, ln2_b + l*HID);

        tgemm_pre<2><<<dim3(MLPD/128, ROWS/128), 256, TG_SMEM>>>(
            y2, HID, W1H + (size_t)l*(HID/2)*MLPD,
            nullptr, MLPD, ROWS, MLPD, HID, b1 + l*MLPD, mlp2);
        tgemm_pre<3><<<dim3(HID/128, ROWS/128), 256, TG_SMEM>>>(
            mlp2, MLPD, W2H + (size_t)l*(MLPD/2)*HID,
            x, HID, ROWS, HID, MLPD, b2 + l*HID, nullptr);
    }

    gemm64<<<dim3((OUTD+63)/64, BATCH/64), 256>>>(x, NTOK*HID, Wout, OUTD,
                                                  logits, OUTD, BATCH, OUTD, HID, bout);
    softmax_kernel<<<BATCH, 256>>>(logits, (float*)d_out);
    (void)n_in; (void)out_size;
}